// round 1
// baseline (speedup 1.0000x reference)
#include <cuda_runtime.h>
#include <math.h>

// ---------------------------------------------------------------------------
// Problem dims (fixed by the reference)
// ---------------------------------------------------------------------------
#define BATCH 2
#define SEQ   2048
#define BTOK  4096          // BATCH*SEQ
#define DMODEL 1024
#define DH    64
#define NH    16
#define INNER 4096
#define LN_EPS 1e-5f

// ---------------------------------------------------------------------------
// Scratch (no cudaMalloc allowed -> __device__ globals)
// ---------------------------------------------------------------------------
__device__ float g_q   [(size_t)BTOK * DMODEL];       // 16 MB
__device__ float g_kv  [(size_t)BTOK * 2 * DH];       //  2 MB
__device__ float g_attn[(size_t)BTOK * DMODEL];       // 16 MB
__device__ float g_proj[(size_t)BTOK * DMODEL];       // 16 MB
__device__ float g_x1  [(size_t)BTOK * DMODEL];       // 16 MB
__device__ float g_h   [(size_t)BTOK * DMODEL];       // 16 MB
__device__ float g_u   [(size_t)BTOK * 2 * INNER];    // 128 MB
__device__ float g_f   [(size_t)BTOK * INNER];        // 64 MB
__device__ float g_ffn [(size_t)BTOK * DMODEL];       // 16 MB

// ---------------------------------------------------------------------------
// SGEMM: C[M,N] = A[M,K] @ B[K,N], all row-major fp32.
// M,N,K multiples of 128/128/16 (true for every call here).
// 128x128 block tile, BK=16, 256 threads, 8x8 microtile.
// ---------------------------------------------------------------------------
#define BM 128
#define BN 128
#define BK 16
#define TM 8
#define TN 8

__global__ void __launch_bounds__(256)
sgemm_kernel(int M, int N, int K,
             const float* __restrict__ A,
             const float* __restrict__ B,
             float* __restrict__ C)
{
    __shared__ float As[BK][BM];   // transposed
    __shared__ float Bs[BK][BN];

    const int tid  = threadIdx.x;
    const int cRow = blockIdx.y;
    const int cCol = blockIdx.x;

    A += (size_t)cRow * BM * K;
    B += (size_t)cCol * BN;
    C += (size_t)cRow * BM * N + (size_t)cCol * BN;

    const int ty = tid >> 4;        // 0..15
    const int tx = tid & 15;        // 0..15

    const int aRow = tid >> 2;          // 0..63
    const int aCol = (tid & 3) * 4;     // 0,4,8,12
    const int bRow = tid >> 5;          // 0..7
    const int bCol = (tid & 31) * 4;    // 0..124

    float acc[TM][TN] = {};
    float regM[TM], regN[TN];

    for (int kt = 0; kt < K; kt += BK) {
        #pragma unroll
        for (int i = 0; i < 2; i++) {
            const int r = aRow + i * 64;
            const float4 v = *(const float4*)(A + (size_t)r * K + aCol);
            As[aCol + 0][r] = v.x;
            As[aCol + 1][r] = v.y;
            As[aCol + 2][r] = v.z;
            As[aCol + 3][r] = v.w;
        }
        #pragma unroll
        for (int i = 0; i < 2; i++) {
            const int r = bRow + i * 8;
            *(float4*)(&Bs[r][bCol]) = *(const float4*)(B + (size_t)r * N + bCol);
        }
        __syncthreads();

        #pragma unroll
        for (int k = 0; k < BK; k++) {
            #pragma unroll
            for (int i = 0; i < TM; i++) regM[i] = As[k][ty * TM + i];
            #pragma unroll
            for (int j = 0; j < TN; j++) regN[j] = Bs[k][tx * TN + j];
            #pragma unroll
            for (int i = 0; i < TM; i++)
                #pragma unroll
                for (int j = 0; j < TN; j++)
                    acc[i][j] += regM[i] * regN[j];
        }
        __syncthreads();
        A += BK;
        B += (size_t)BK * N;
    }

    #pragma unroll
    for (int i = 0; i < TM; i++) {
        #pragma unroll
        for (int j = 0; j < TN; j += 4) {
            float4 v = make_float4(acc[i][j], acc[i][j+1], acc[i][j+2], acc[i][j+3]);
            *(float4*)(C + (size_t)(ty * TM + i) * N + tx * TN + j) = v;
        }
    }
}

// ---------------------------------------------------------------------------
// Flash attention, K/V shared across heads.
// q:   [BTOK, NH, DH]  (i.e. (B,L,H,dh) flattened)
// kv:  [BTOK, 2*DH]    cols 0..63 = K, 64..127 = V
// out: [BTOK, NH, DH]
// grid: (SEQ/32, NH, BATCH), 128 threads.
// Each thread owns 2 query rows (r, r+16) and an 8-wide key/dim slice (g).
// ---------------------------------------------------------------------------
__global__ void __launch_bounds__(128)
attn_kernel(const float* __restrict__ q,
            const float* __restrict__ kv,
            float* __restrict__ out)
{
    __shared__ float Qs[32][65];
    __shared__ float Ks[64][65];   // reused for V
    __shared__ float Ps[32][65];

    const int t = threadIdx.x;
    const int r = t >> 3;          // 0..15
    const int g = t & 7;           // 0..7
    const int qt = blockIdx.x;
    const int h  = blockIdx.y;
    const int b  = blockIdx.z;
    const int q0 = qt * 32;

    // Load Q tile: 32 rows x 64 dims, 16 floats/thread
    {
        const int row = t >> 2;             // 0..31
        const int seg = (t & 3) * 16;
        const float* src = q + (((size_t)(b * SEQ + q0 + row) * NH + h) * DH) + seg;
        #pragma unroll
        for (int i = 0; i < 16; i++) Qs[row][seg + i] = src[i];
    }

    float m[2] = {-1e30f, -1e30f};
    float l[2] = {0.f, 0.f};
    float o[2][8] = {};
    const float scale = 0.125f;    // 1/sqrt(64)

    for (int jt = 0; jt < SEQ; jt += 64) {
        __syncthreads();   // previous iter's Ps/Ks reads done; also covers Qs fill (iter 0)

        // Load K tile: 64 rows x 64 dims, 32 floats/thread
        {
            const int row = t >> 1;
            const int seg = (t & 1) * 32;
            const float* src = kv + ((size_t)(b * SEQ + jt + row) * 128) + seg;
            #pragma unroll
            for (int i = 0; i < 32; i++) Ks[row][seg + i] = src[i];
        }
        __syncthreads();

        // S = Q K^T (each thread: 2 rows x 8 keys)
        float s[2][8] = {};
        #pragma unroll 8
        for (int d = 0; d < 64; d++) {
            const float q0v = Qs[r][d];
            const float q1v = Qs[r + 16][d];
            #pragma unroll
            for (int kk = 0; kk < 8; kk++) {
                const float kvv = Ks[g * 8 + kk][d];
                s[0][kk] += q0v * kvv;
                s[1][kk] += q1v * kvv;
            }
        }

        #pragma unroll
        for (int rr = 0; rr < 2; rr++) {
            float mt = -1e30f;
            #pragma unroll
            for (int kk = 0; kk < 8; kk++) {
                s[rr][kk] *= scale;
                mt = fmaxf(mt, s[rr][kk]);
            }
            #pragma unroll
            for (int off = 1; off < 8; off <<= 1)
                mt = fmaxf(mt, __shfl_xor_sync(0xffffffffu, mt, off));

            const float mnew = fmaxf(m[rr], mt);
            const float fac  = __expf(m[rr] - mnew);
            float ts = 0.f;
            const int prow = rr ? r + 16 : r;
            #pragma unroll
            for (int kk = 0; kk < 8; kk++) {
                const float p = __expf(s[rr][kk] - mnew);
                Ps[prow][g * 8 + kk] = p;
                ts += p;
            }
            #pragma unroll
            for (int off = 1; off < 8; off <<= 1)
                ts += __shfl_xor_sync(0xffffffffu, ts, off);

            l[rr] = l[rr] * fac + ts;
            m[rr] = mnew;
            #pragma unroll
            for (int dd = 0; dd < 8; dd++) o[rr][dd] *= fac;
        }
        __syncthreads();   // Ps written, K reads done

        // Load V tile over Ks
        {
            const int row = t >> 1;
            const int seg = (t & 1) * 32;
            const float* src = kv + ((size_t)(b * SEQ + jt + row) * 128) + 64 + seg;
            #pragma unroll
            for (int i = 0; i < 32; i++) Ks[row][seg + i] = src[i];
        }
        __syncthreads();

        // O += P V (each thread: 2 rows x 8 dims)
        #pragma unroll 8
        for (int k2 = 0; k2 < 64; k2++) {
            const float p0 = Ps[r][k2];
            const float p1 = Ps[r + 16][k2];
            #pragma unroll
            for (int dd = 0; dd < 8; dd++) {
                const float vv = Ks[k2][g * 8 + dd];
                o[0][dd] += p0 * vv;
                o[1][dd] += p1 * vv;
            }
        }
    }

    #pragma unroll
    for (int rr = 0; rr < 2; rr++) {
        const int row = rr ? r + 16 : r;
        const float inv = 1.f / l[rr];
        float* dst = out + (((size_t)(b * SEQ + q0 + row) * NH + h) * DH) + g * 8;
        #pragma unroll
        for (int dd = 0; dd < 8; dd++) dst[dd] = o[rr][dd] * inv;
    }
}

// ---------------------------------------------------------------------------
// Block reduce helper (256 threads)
// ---------------------------------------------------------------------------
__device__ __forceinline__ float block_reduce_sum(float v, float* scratch)
{
    __syncthreads();  // protect scratch reuse from prior call
    const int lane = threadIdx.x & 31;
    const int w    = threadIdx.x >> 5;
    #pragma unroll
    for (int off = 16; off; off >>= 1) v += __shfl_xor_sync(0xffffffffu, v, off);
    if (lane == 0) scratch[w] = v;
    __syncthreads();
    if (w == 0) {
        float x = (lane < (int)(blockDim.x >> 5)) ? scratch[lane] : 0.f;
        #pragma unroll
        for (int off = 16; off; off >>= 1) x += __shfl_xor_sync(0xffffffffu, x, off);
        if (lane == 0) scratch[0] = x;
    }
    __syncthreads();
    return scratch[0];
}

// ---------------------------------------------------------------------------
// x1 = LN(x + proj) * gamma1 ;  h = LN(x1) * gamma_ffn
// one block per token row
// ---------------------------------------------------------------------------
__global__ void __launch_bounds__(256)
ln_dual_kernel(const float* __restrict__ x, const float* __restrict__ pj,
               const float* __restrict__ g1, const float* __restrict__ gf,
               float* __restrict__ x1, float* __restrict__ h)
{
    __shared__ float buf[DMODEL];
    __shared__ float scr[32];
    const size_t row = blockIdx.x;
    const float* xr = x  + row * DMODEL;
    const float* pr = pj + row * DMODEL;

    float sum = 0.f, sq = 0.f;
    for (int i = threadIdx.x; i < DMODEL; i += 256) {
        const float v = xr[i] + pr[i];
        buf[i] = v; sum += v; sq += v * v;
    }
    sum = block_reduce_sum(sum, scr);
    sq  = block_reduce_sum(sq,  scr);
    const float mu  = sum * (1.f / DMODEL);
    const float var = sq * (1.f / DMODEL) - mu * mu;
    const float rs  = rsqrtf(var + LN_EPS);

    float sum2 = 0.f, sq2 = 0.f;
    for (int i = threadIdx.x; i < DMODEL; i += 256) {
        const float v = (buf[i] - mu) * rs * g1[i];
        x1[row * DMODEL + i] = v;
        buf[i] = v; sum2 += v; sq2 += v * v;
    }
    sum2 = block_reduce_sum(sum2, scr);
    sq2  = block_reduce_sum(sq2,  scr);
    const float mu2  = sum2 * (1.f / DMODEL);
    const float var2 = sq2 * (1.f / DMODEL) - mu2 * mu2;
    const float rs2  = rsqrtf(var2 + LN_EPS);

    for (int i = threadIdx.x; i < DMODEL; i += 256)
        h[row * DMODEL + i] = (buf[i] - mu2) * rs2 * gf[i];
}

// ---------------------------------------------------------------------------
// out = LN(a + b) * gamma
// ---------------------------------------------------------------------------
__global__ void __launch_bounds__(256)
ln_final_kernel(const float* __restrict__ a, const float* __restrict__ bb,
                const float* __restrict__ gm, float* __restrict__ outp)
{
    __shared__ float buf[DMODEL];
    __shared__ float scr[32];
    const size_t row = blockIdx.x;
    const float* ar = a  + row * DMODEL;
    const float* br = bb + row * DMODEL;

    float sum = 0.f, sq = 0.f;
    for (int i = threadIdx.x; i < DMODEL; i += 256) {
        const float v = ar[i] + br[i];
        buf[i] = v; sum += v; sq += v * v;
    }
    sum = block_reduce_sum(sum, scr);
    sq  = block_reduce_sum(sq,  scr);
    const float mu  = sum * (1.f / DMODEL);
    const float var = sq * (1.f / DMODEL) - mu * mu;
    const float rs  = rsqrtf(var + LN_EPS);

    for (int i = threadIdx.x; i < DMODEL; i += 256)
        outp[row * DMODEL + i] = (buf[i] - mu) * rs * gm[i];
}

// ---------------------------------------------------------------------------
// f = gelu_exact(u[:, INNER:]) * u[:, :INNER]
// ---------------------------------------------------------------------------
__global__ void __launch_bounds__(256)
gelu_mul_kernel(const float* __restrict__ u, float* __restrict__ f)
{
    const size_t idx = (size_t)blockIdx.x * blockDim.x + threadIdx.x;  // float4 index
    const size_t n4  = (size_t)BTOK * INNER / 4;
    if (idx >= n4) return;
    const size_t e   = idx * 4;
    const size_t row = e >> 12;             // / INNER
    const size_t col = e & (INNER - 1);
    const float4 a  = *(const float4*)(u + row * (2 * INNER) + col);
    const float4 gt = *(const float4*)(u + row * (2 * INNER) + INNER + col);
    float4 rv;
    rv.x = 0.5f * gt.x * (1.f + erff(gt.x * 0.70710678118654752f)) * a.x;
    rv.y = 0.5f * gt.y * (1.f + erff(gt.y * 0.70710678118654752f)) * a.y;
    rv.z = 0.5f * gt.z * (1.f + erff(gt.z * 0.70710678118654752f)) * a.z;
    rv.w = 0.5f * gt.w * (1.f + erff(gt.w * 0.70710678118654752f)) * a.w;
    *(float4*)(f + e) = rv;
}

// ---------------------------------------------------------------------------
// Launch
// ---------------------------------------------------------------------------
extern "C" void kernel_launch(void* const* d_in, const int* in_sizes, int n_in,
                              void* d_out, int out_size)
{
    const float* x        = (const float*)d_in[0];
    const float* w_q      = (const float*)d_in[1];
    const float* w_kv     = (const float*)d_in[2];
    const float* w_concat = (const float*)d_in[3];
    const float* gamma1   = (const float*)d_in[4];
    const float* gammaffn = (const float*)d_in[5];
    const float* w_ff1    = (const float*)d_in[6];
    const float* w_ff2    = (const float*)d_in[7];
    const float* gamma2   = (const float*)d_in[8];
    float* out = (float*)d_out;

    float *q, *kvp, *attn, *proj, *x1, *h, *u, *f, *ffn;
    cudaGetSymbolAddress((void**)&q,    g_q);
    cudaGetSymbolAddress((void**)&kvp,  g_kv);
    cudaGetSymbolAddress((void**)&attn, g_attn);
    cudaGetSymbolAddress((void**)&proj, g_proj);
    cudaGetSymbolAddress((void**)&x1,   g_x1);
    cudaGetSymbolAddress((void**)&h,    g_h);
    cudaGetSymbolAddress((void**)&u,    g_u);
    cudaGetSymbolAddress((void**)&f,    g_f);
    cudaGetSymbolAddress((void**)&ffn,  g_ffn);

    // 1) q = x @ w_q   [4096,1024]
    sgemm_kernel<<<dim3(DMODEL / BN, BTOK / BM), 256>>>(BTOK, DMODEL, DMODEL, x, w_q, q);
    // 2) kv = x @ w_kv [4096,128]
    sgemm_kernel<<<dim3(128 / BN, BTOK / BM), 256>>>(BTOK, 128, DMODEL, x, w_kv, kvp);
    // 3) attention
    attn_kernel<<<dim3(SEQ / 32, NH, BATCH), 128>>>(q, kvp, attn);
    // 4) proj = attn @ w_concat
    sgemm_kernel<<<dim3(DMODEL / BN, BTOK / BM), 256>>>(BTOK, DMODEL, DMODEL, attn, w_concat, proj);
    // 5) x1 = LN(x+proj)*g1 ; h = LN(x1)*gffn
    ln_dual_kernel<<<BTOK, 256>>>(x, proj, gamma1, gammaffn, x1, h);
    // 6) u = h @ w_ff1 [4096,8192]
    sgemm_kernel<<<dim3(2 * INNER / BN, BTOK / BM), 256>>>(BTOK, 2 * INNER, DMODEL, h, w_ff1, u);
    // 7) f = gelu(gate)*a
    {
        const size_t n4 = (size_t)BTOK * INNER / 4;
        gelu_mul_kernel<<<(unsigned)((n4 + 255) / 256), 256>>>(u, f);
    }
    // 8) ffn = f @ w_ff2 [4096,1024]
    sgemm_kernel<<<dim3(DMODEL / BN, BTOK / BM), 256>>>(BTOK, DMODEL, INNER, f, w_ff2, ffn);
    // 9) out = LN(x1+ffn)*g2
    ln_final_kernel<<<BTOK, 256>>>(x1, ffn, gamma2, out);
}

// round 2
// speedup vs baseline: 3.6108x; 3.6108x over previous
#include <cuda_runtime.h>
#include <math.h>
#include <stdint.h>

// ---------------------------------------------------------------------------
// Problem dims (fixed by the reference)
// ---------------------------------------------------------------------------
#define BATCH 2
#define SEQ   2048
#define BTOK  4096          // BATCH*SEQ
#define DMODEL 1024
#define DH    64
#define NH    16
#define INNER 4096
#define LN_EPS 1e-5f

// ---------------------------------------------------------------------------
// Scratch (no cudaMalloc -> __device__ globals)
// ---------------------------------------------------------------------------
__device__ float g_q   [(size_t)BTOK * DMODEL];            // 16 MB
__device__ float g_kv  [(size_t)BTOK * 2 * DH];            //  2 MB
__device__ float g_s   [(size_t)BATCH * NH * SEQ * SEQ];   // 536 MB (scores)
__device__ float g_attn[(size_t)BTOK * DMODEL];            // 16 MB
__device__ float g_proj[(size_t)BTOK * DMODEL];            // 16 MB
__device__ float g_x1  [(size_t)BTOK * DMODEL];            // 16 MB
__device__ float g_h   [(size_t)BTOK * DMODEL];            // 16 MB
__device__ float g_u   [(size_t)BTOK * 2 * INNER];         // 128 MB
__device__ float g_f   [(size_t)BTOK * INNER];             // 64 MB
__device__ float g_ffn [(size_t)BTOK * DMODEL];            // 16 MB

// ---------------------------------------------------------------------------
// tf32 helpers
// ---------------------------------------------------------------------------
__device__ __forceinline__ uint32_t f2tf32(float x) {
    uint32_t r;
    asm("cvt.rna.tf32.f32 %0, %1;" : "=r"(r) : "f"(x));
    return r;
}

__device__ __forceinline__ void mma_tf32(float* c, const uint32_t* a, const uint32_t* b) {
    asm("mma.sync.aligned.m16n8k8.row.col.f32.tf32.tf32.f32 "
        "{%0,%1,%2,%3}, {%4,%5,%6,%7}, {%8,%9}, {%0,%1,%2,%3};"
        : "+f"(c[0]), "+f"(c[1]), "+f"(c[2]), "+f"(c[3])
        : "r"(a[0]), "r"(a[1]), "r"(a[2]), "r"(a[3]),
          "r"(b[0]), "r"(b[1]));
}

// ---------------------------------------------------------------------------
// Tensor-core GEMM (tf32 in, fp32 accumulate)
// C[M,N] = A[M,K] @ op(B),  op(B) = B[K,N] (NN) or B[N,K]^T (NT via BT=true)
// BM=128 fixed, BN template (128 or 64), BK=16, 256 threads = 8 warps (4x2).
// Strided batching: batch z decomposes as outer = z/16, inner = z%16.
// Requirements (all satisfied here): M%128==0, N%BN==0, K%16==0.
// ---------------------------------------------------------------------------
template<int BN, bool BT>
__global__ void __launch_bounds__(256, 2)
tc_gemm(int K,
        const float* __restrict__ A, int lda, long sAo, long sAi,
        const float* __restrict__ B, int ldb, long sBo, long sBi,
        float*       __restrict__ C, int ldc, long sCo, long sCi)
{
    constexpr int BM = 128, BK = 16;
    constexpr int SA = 136;
    constexpr int SB = (BN == 128) ? 136 : 72;
    constexpr int WN = BN / 16;          // n-tiles per warp (8 or 4)

    __shared__ uint32_t As[BK * SA];     // [k][m], tf32 bits
    __shared__ uint32_t Bs[BK * SB];     // [k][n], tf32 bits

    const int tid  = threadIdx.x;
    const int warp = tid >> 5;
    const int lane = tid & 31;
    const int wm   = warp >> 1;          // 0..3
    const int wn   = warp & 1;           // 0..1
    const int g    = lane >> 2;          // 0..7
    const int t    = lane & 3;           // 0..3

    const int z = blockIdx.z;
    A += (long)(z >> 4) * sAo + (long)(z & 15) * sAi;
    B += (long)(z >> 4) * sBo + (long)(z & 15) * sBi;
    C += (long)(z >> 4) * sCo + (long)(z & 15) * sCi;

    const int m0 = blockIdx.y * BM;
    const int n0 = blockIdx.x * BN;

    // ---- staging thread mapping ----
    const int rA = tid >> 2;             // 0..63 (row within tile, +64 for 2nd)
    const int cA = (tid & 3) * 4;        // k offset 0,4,8,12
    const float* Aptr = A + (size_t)(m0 + rA) * lda + cA;

    const float* Bptr;
    int kB = 0, nB = 0;
    if (BT) {
        Bptr = B + (size_t)(n0 + rA) * ldb + cA;      // transpose-stage like A
    } else if (BN == 128) {
        kB = tid >> 5; nB = (tid & 31) * 4;
        Bptr = B + (size_t)kB * ldb + n0 + nB;
    } else {
        kB = tid >> 4; nB = (tid & 15) * 4;
        Bptr = B + (size_t)kB * ldb + n0 + nB;
    }

    float acc[2][WN][4];
    #pragma unroll
    for (int mi = 0; mi < 2; mi++)
        #pragma unroll
        for (int ni = 0; ni < WN; ni++)
            #pragma unroll
            for (int j = 0; j < 4; j++) acc[mi][ni][j] = 0.f;

    float4 a0, a1, b0, b1;

    // prologue loads (tile 0)
    a0 = *(const float4*)(Aptr);
    a1 = *(const float4*)(Aptr + (size_t)64 * lda);
    if (BT) {
        b0 = *(const float4*)(Bptr);
        b1 = *(const float4*)(Bptr + (size_t)64 * ldb);
    } else if (BN == 128) {
        b0 = *(const float4*)(Bptr);
        b1 = *(const float4*)(Bptr + (size_t)8 * ldb);
    } else {
        b0 = *(const float4*)(Bptr);
    }

    for (int kt = 0; kt < K; kt += BK) {
        // ---- store regs -> smem (tf32 convert) ----
        {
            const float* av0 = (const float*)&a0;
            const float* av1 = (const float*)&a1;
            #pragma unroll
            for (int j = 0; j < 4; j++) {
                As[(cA + j) * SA + rA]      = f2tf32(av0[j]);
                As[(cA + j) * SA + rA + 64] = f2tf32(av1[j]);
            }
            if (BT) {
                const float* bv0 = (const float*)&b0;
                const float* bv1 = (const float*)&b1;
                #pragma unroll
                for (int j = 0; j < 4; j++) {
                    Bs[(cA + j) * SB + rA]      = f2tf32(bv0[j]);
                    Bs[(cA + j) * SB + rA + 64] = f2tf32(bv1[j]);
                }
            } else if (BN == 128) {
                const float* bv0 = (const float*)&b0;
                const float* bv1 = (const float*)&b1;
                #pragma unroll
                for (int j = 0; j < 4; j++) {
                    Bs[kB * SB + nB + j]       = f2tf32(bv0[j]);
                    Bs[(kB + 8) * SB + nB + j] = f2tf32(bv1[j]);
                }
            } else {
                const float* bv0 = (const float*)&b0;
                #pragma unroll
                for (int j = 0; j < 4; j++)
                    Bs[kB * SB + nB + j] = f2tf32(bv0[j]);
            }
        }
        __syncthreads();

        // ---- prefetch next tile into regs ----
        if (kt + BK < K) {
            Aptr += BK;
            a0 = *(const float4*)(Aptr);
            a1 = *(const float4*)(Aptr + (size_t)64 * lda);
            if (BT) {
                Bptr += BK;
                b0 = *(const float4*)(Bptr);
                b1 = *(const float4*)(Bptr + (size_t)64 * ldb);
            } else if (BN == 128) {
                Bptr += (size_t)BK * ldb;
                b0 = *(const float4*)(Bptr);
                b1 = *(const float4*)(Bptr + (size_t)8 * ldb);
            } else {
                Bptr += (size_t)BK * ldb;
                b0 = *(const float4*)(Bptr);
            }
        }

        // ---- compute: 2 k-steps of 8 ----
        #pragma unroll
        for (int ks = 0; ks < 2; ks++) {
            const int kb = ks * 8;
            uint32_t af[2][4];
            uint32_t bf[WN][2];
            #pragma unroll
            for (int mi = 0; mi < 2; mi++) {
                const int row = wm * 32 + mi * 16;
                af[mi][0] = As[(kb + t) * SA + row + g];
                af[mi][1] = As[(kb + t) * SA + row + g + 8];
                af[mi][2] = As[(kb + t + 4) * SA + row + g];
                af[mi][3] = As[(kb + t + 4) * SA + row + g + 8];
            }
            #pragma unroll
            for (int ni = 0; ni < WN; ni++) {
                const int col = wn * (BN / 2) + ni * 8 + g;
                bf[ni][0] = Bs[(kb + t) * SB + col];
                bf[ni][1] = Bs[(kb + t + 4) * SB + col];
            }
            #pragma unroll
            for (int mi = 0; mi < 2; mi++)
                #pragma unroll
                for (int ni = 0; ni < WN; ni++)
                    mma_tf32(acc[mi][ni], af[mi], bf[ni]);
        }
        __syncthreads();
    }

    // ---- epilogue ----
    #pragma unroll
    for (int mi = 0; mi < 2; mi++) {
        #pragma unroll
        for (int ni = 0; ni < WN; ni++) {
            const int r = m0 + wm * 32 + mi * 16 + g;
            const int c = n0 + wn * (BN / 2) + ni * 8 + t * 2;
            *(float2*)&C[(size_t)r * ldc + c] =
                make_float2(acc[mi][ni][0], acc[mi][ni][1]);
            *(float2*)&C[(size_t)(r + 8) * ldc + c] =
                make_float2(acc[mi][ni][2], acc[mi][ni][3]);
        }
    }
}

// ---------------------------------------------------------------------------
// Block reduce helpers (256 threads)
// ---------------------------------------------------------------------------
__device__ __forceinline__ float block_reduce_sum(float v, float* scratch)
{
    __syncthreads();
    const int lane = threadIdx.x & 31;
    const int w    = threadIdx.x >> 5;
    #pragma unroll
    for (int off = 16; off; off >>= 1) v += __shfl_xor_sync(0xffffffffu, v, off);
    if (lane == 0) scratch[w] = v;
    __syncthreads();
    if (w == 0) {
        float x = (lane < 8) ? scratch[lane] : 0.f;
        #pragma unroll
        for (int off = 4; off; off >>= 1) x += __shfl_xor_sync(0xffffffffu, x, off);
        if (lane == 0) scratch[0] = x;
    }
    __syncthreads();
    return scratch[0];
}

__device__ __forceinline__ float block_reduce_max(float v, float* scratch)
{
    __syncthreads();
    const int lane = threadIdx.x & 31;
    const int w    = threadIdx.x >> 5;
    #pragma unroll
    for (int off = 16; off; off >>= 1) v = fmaxf(v, __shfl_xor_sync(0xffffffffu, v, off));
    if (lane == 0) scratch[w] = v;
    __syncthreads();
    if (w == 0) {
        float x = (lane < 8) ? scratch[lane] : -1e30f;
        #pragma unroll
        for (int off = 4; off; off >>= 1) x = fmaxf(x, __shfl_xor_sync(0xffffffffu, x, off));
        if (lane == 0) scratch[0] = x;
    }
    __syncthreads();
    return scratch[0];
}

// ---------------------------------------------------------------------------
// In-place softmax over rows of S (row length SEQ=2048), with 1/8 scaling.
// One block (256 threads) per row; 8 floats per thread, kept in registers.
// ---------------------------------------------------------------------------
__global__ void __launch_bounds__(256)
softmax_kernel(float* __restrict__ S)
{
    __shared__ float scr[32];
    float* row = S + (size_t)blockIdx.x * SEQ;
    float4* r4 = (float4*)row;

    float4 v0 = r4[threadIdx.x];
    float4 v1 = r4[threadIdx.x + 256];
    const float scale = 0.125f;   // 1/sqrt(64)
    v0.x *= scale; v0.y *= scale; v0.z *= scale; v0.w *= scale;
    v1.x *= scale; v1.y *= scale; v1.z *= scale; v1.w *= scale;

    float mx = fmaxf(fmaxf(fmaxf(v0.x, v0.y), fmaxf(v0.z, v0.w)),
                     fmaxf(fmaxf(v1.x, v1.y), fmaxf(v1.z, v1.w)));
    mx = block_reduce_max(mx, scr);

    v0.x = __expf(v0.x - mx); v0.y = __expf(v0.y - mx);
    v0.z = __expf(v0.z - mx); v0.w = __expf(v0.w - mx);
    v1.x = __expf(v1.x - mx); v1.y = __expf(v1.y - mx);
    v1.z = __expf(v1.z - mx); v1.w = __expf(v1.w - mx);

    float s = v0.x + v0.y + v0.z + v0.w + v1.x + v1.y + v1.z + v1.w;
    s = block_reduce_sum(s, scr);
    const float inv = 1.f / s;

    v0.x *= inv; v0.y *= inv; v0.z *= inv; v0.w *= inv;
    v1.x *= inv; v1.y *= inv; v1.z *= inv; v1.w *= inv;
    r4[threadIdx.x]       = v0;
    r4[threadIdx.x + 256] = v1;
}

// ---------------------------------------------------------------------------
// x1 = LN(x + proj) * gamma1 ;  h = LN(x1) * gamma_ffn
// ---------------------------------------------------------------------------
__global__ void __launch_bounds__(256)
ln_dual_kernel(const float* __restrict__ x, const float* __restrict__ pj,
               const float* __restrict__ g1, const float* __restrict__ gf,
               float* __restrict__ x1, float* __restrict__ h)
{
    __shared__ float buf[DMODEL];
    __shared__ float scr[32];
    const size_t row = blockIdx.x;
    const float* xr = x  + row * DMODEL;
    const float* pr = pj + row * DMODEL;

    float sum = 0.f, sq = 0.f;
    for (int i = threadIdx.x; i < DMODEL; i += 256) {
        const float v = xr[i] + pr[i];
        buf[i] = v; sum += v; sq += v * v;
    }
    sum = block_reduce_sum(sum, scr);
    sq  = block_reduce_sum(sq,  scr);
    const float mu  = sum * (1.f / DMODEL);
    const float var = sq * (1.f / DMODEL) - mu * mu;
    const float rs  = rsqrtf(var + LN_EPS);

    float sum2 = 0.f, sq2 = 0.f;
    for (int i = threadIdx.x; i < DMODEL; i += 256) {
        const float v = (buf[i] - mu) * rs * g1[i];
        x1[row * DMODEL + i] = v;
        buf[i] = v; sum2 += v; sq2 += v * v;
    }
    sum2 = block_reduce_sum(sum2, scr);
    sq2  = block_reduce_sum(sq2,  scr);
    const float mu2  = sum2 * (1.f / DMODEL);
    const float var2 = sq2 * (1.f / DMODEL) - mu2 * mu2;
    const float rs2  = rsqrtf(var2 + LN_EPS);

    for (int i = threadIdx.x; i < DMODEL; i += 256)
        h[row * DMODEL + i] = (buf[i] - mu2) * rs2 * gf[i];
}

// ---------------------------------------------------------------------------
// out = LN(a + b) * gamma
// ---------------------------------------------------------------------------
__global__ void __launch_bounds__(256)
ln_final_kernel(const float* __restrict__ a, const float* __restrict__ bb,
                const float* __restrict__ gm, float* __restrict__ outp)
{
    __shared__ float buf[DMODEL];
    __shared__ float scr[32];
    const size_t row = blockIdx.x;
    const float* ar = a  + row * DMODEL;
    const float* br = bb + row * DMODEL;

    float sum = 0.f, sq = 0.f;
    for (int i = threadIdx.x; i < DMODEL; i += 256) {
        const float v = ar[i] + br[i];
        buf[i] = v; sum += v; sq += v * v;
    }
    sum = block_reduce_sum(sum, scr);
    sq  = block_reduce_sum(sq,  scr);
    const float mu  = sum * (1.f / DMODEL);
    const float var = sq * (1.f / DMODEL) - mu * mu;
    const float rs  = rsqrtf(var + LN_EPS);

    for (int i = threadIdx.x; i < DMODEL; i += 256)
        outp[row * DMODEL + i] = (buf[i] - mu) * rs * gm[i];
}

// ---------------------------------------------------------------------------
// f = gelu_exact(u[:, INNER:]) * u[:, :INNER]
// ---------------------------------------------------------------------------
__global__ void __launch_bounds__(256)
gelu_mul_kernel(const float* __restrict__ u, float* __restrict__ f)
{
    const size_t idx = (size_t)blockIdx.x * blockDim.x + threadIdx.x;
    const size_t n4  = (size_t)BTOK * INNER / 4;
    if (idx >= n4) return;
    const size_t e   = idx * 4;
    const size_t row = e >> 12;
    const size_t col = e & (INNER - 1);
    const float4 a  = *(const float4*)(u + row * (2 * INNER) + col);
    const float4 gt = *(const float4*)(u + row * (2 * INNER) + INNER + col);
    float4 rv;
    rv.x = 0.5f * gt.x * (1.f + erff(gt.x * 0.70710678118654752f)) * a.x;
    rv.y = 0.5f * gt.y * (1.f + erff(gt.y * 0.70710678118654752f)) * a.y;
    rv.z = 0.5f * gt.z * (1.f + erff(gt.z * 0.70710678118654752f)) * a.z;
    rv.w = 0.5f * gt.w * (1.f + erff(gt.w * 0.70710678118654752f)) * a.w;
    *(float4*)(f + e) = rv;
}

// ---------------------------------------------------------------------------
// Launch
// ---------------------------------------------------------------------------
extern "C" void kernel_launch(void* const* d_in, const int* in_sizes, int n_in,
                              void* d_out, int out_size)
{
    const float* x        = (const float*)d_in[0];
    const float* w_q      = (const float*)d_in[1];
    const float* w_kv     = (const float*)d_in[2];
    const float* w_concat = (const float*)d_in[3];
    const float* gamma1   = (const float*)d_in[4];
    const float* gammaffn = (const float*)d_in[5];
    const float* w_ff1    = (const float*)d_in[6];
    const float* w_ff2    = (const float*)d_in[7];
    const float* gamma2   = (const float*)d_in[8];
    float* out = (float*)d_out;

    float *q, *kvp, *S, *attn, *proj, *x1, *h, *u, *f, *ffn;
    cudaGetSymbolAddress((void**)&q,    g_q);
    cudaGetSymbolAddress((void**)&kvp,  g_kv);
    cudaGetSymbolAddress((void**)&S,    g_s);
    cudaGetSymbolAddress((void**)&attn, g_attn);
    cudaGetSymbolAddress((void**)&proj, g_proj);
    cudaGetSymbolAddress((void**)&x1,   g_x1);
    cudaGetSymbolAddress((void**)&h,    g_h);
    cudaGetSymbolAddress((void**)&u,    g_u);
    cudaGetSymbolAddress((void**)&f,    g_f);
    cudaGetSymbolAddress((void**)&ffn,  g_ffn);

    const long LL  = (long)SEQ * SEQ;           // 4194304

    // 1) q = x @ w_q   [4096,1024]
    tc_gemm<128,false><<<dim3(8, 32, 1), 256>>>(DMODEL,
        x,    DMODEL, 0, 0,  w_q, DMODEL, 0, 0,  q, DMODEL, 0, 0);
    // 2) kv = x @ w_kv [4096,128]
    tc_gemm<128,false><<<dim3(1, 32, 1), 256>>>(DMODEL,
        x,    DMODEL, 0, 0,  w_kv, 128, 0, 0,   kvp, 128, 0, 0);
    // 3) S[b,h] = Q[b,h] @ K[b]^T   (batched NT, K=64)
    tc_gemm<128,true><<<dim3(SEQ/128, SEQ/128, BATCH*NH), 256>>>(DH,
        q,   DMODEL, (long)SEQ*DMODEL, DH,
        kvp, 128,    (long)SEQ*128,    0,
        S,   SEQ,    (long)NH*LL,      LL);
    // 4) softmax rows of S (with 1/sqrt(dh) scaling)
    softmax_kernel<<<BATCH*NH*SEQ, 256>>>(S);
    // 5) attn[b,q,h,:] = P[b,h] @ V[b]   (batched NN, N=64)
    tc_gemm<64,false><<<dim3(1, SEQ/128, BATCH*NH), 256>>>(SEQ,
        S,        SEQ, (long)NH*LL,      LL,
        kvp + DH, 128, (long)SEQ*128,    0,
        attn,     DMODEL, (long)SEQ*DMODEL, DH);
    // 6) proj = attn @ w_concat
    tc_gemm<128,false><<<dim3(8, 32, 1), 256>>>(DMODEL,
        attn, DMODEL, 0, 0,  w_concat, DMODEL, 0, 0,  proj, DMODEL, 0, 0);
    // 7) x1 = LN(x+proj)*g1 ; h = LN(x1)*gffn
    ln_dual_kernel<<<BTOK, 256>>>(x, proj, gamma1, gammaffn, x1, h);
    // 8) u = h @ w_ff1 [4096,8192]
    tc_gemm<128,false><<<dim3(64, 32, 1), 256>>>(DMODEL,
        h, DMODEL, 0, 0,  w_ff1, 2*INNER, 0, 0,  u, 2*INNER, 0, 0);
    // 9) f = gelu(gate)*a
    {
        const size_t n4 = (size_t)BTOK * INNER / 4;
        gelu_mul_kernel<<<(unsigned)((n4 + 255) / 256), 256>>>(u, f);
    }
    // 10) ffn = f @ w_ff2 [4096,1024]
    tc_gemm<128,false><<<dim3(8, 32, 1), 256>>>(INNER,
        f, INNER, 0, 0,  w_ff2, DMODEL, 0, 0,  ffn, DMODEL, 0, 0);
    // 11) out = LN(x1+ffn)*g2
    ln_final_kernel<<<BTOK, 256>>>(x1, ffn, gamma2, out);
}

// round 5
// speedup vs baseline: 4.7812x; 1.3241x over previous
#include <cuda_runtime.h>
#include <math.h>
#include <stdint.h>

// ---------------------------------------------------------------------------
// Problem dims (fixed by the reference)
// ---------------------------------------------------------------------------
#define BATCH 2
#define SEQ   2048
#define BTOK  4096          // BATCH*SEQ
#define DMODEL 1024
#define DH    64
#define NH    16
#define INNER 4096
#define LN_EPS 1e-5f

// ---------------------------------------------------------------------------
// Scratch (no cudaMalloc -> __device__ globals)
// ---------------------------------------------------------------------------
__device__ float g_q   [(size_t)BTOK * DMODEL];            // 16 MB
__device__ float g_kv  [(size_t)BTOK * 2 * DH];            //  2 MB
__device__ float g_attn[(size_t)BTOK * DMODEL];            // 16 MB
__device__ float g_proj[(size_t)BTOK * DMODEL];            // 16 MB
__device__ float g_x1  [(size_t)BTOK * DMODEL];            // 16 MB
__device__ float g_h   [(size_t)BTOK * DMODEL];            // 16 MB
__device__ float g_u   [(size_t)BTOK * 2 * INNER];         // 128 MB
__device__ float g_f   [(size_t)BTOK * INNER];             // 64 MB
__device__ float g_ffn [(size_t)BTOK * DMODEL];            // 16 MB

// ---------------------------------------------------------------------------
// mma + cp.async helpers. tf32 mma reads bits [31:13] of the operand regs,
// so raw fp32 bits == tf32 with RZ rounding (no cvt needed).
// ---------------------------------------------------------------------------
__device__ __forceinline__ void mma_tf32(float* c, const uint32_t* a, const uint32_t* b) {
    asm("mma.sync.aligned.m16n8k8.row.col.f32.tf32.tf32.f32 "
        "{%0,%1,%2,%3}, {%4,%5,%6,%7}, {%8,%9}, {%0,%1,%2,%3};"
        : "+f"(c[0]), "+f"(c[1]), "+f"(c[2]), "+f"(c[3])
        : "r"(a[0]), "r"(a[1]), "r"(a[2]), "r"(a[3]),
          "r"(b[0]), "r"(b[1]));
}

__device__ __forceinline__ void cp_async16(void* smem, const void* gmem) {
    uint32_t s = (uint32_t)__cvta_generic_to_shared(smem);
    asm volatile("cp.async.cg.shared.global [%0], [%1], 16;" :: "r"(s), "l"(gmem));
}
__device__ __forceinline__ void cp_commit() {
    asm volatile("cp.async.commit_group;");
}
template<int N> __device__ __forceinline__ void cp_wait() {
    asm volatile("cp.async.wait_group %0;" :: "n"(N));
}

// ---------------------------------------------------------------------------
// Tensor-core NN GEMM, fp32 in (tf32 truncated), fp32 accumulate.
// C[M,N] = A[M,K] @ B[K,N].  BM=128, BN=128, BK=16, 256 threads = 8 warps.
// 2-stage cp.async pipeline, one __syncthreads per K-tile.
// As layout [m][k] stride 20; Bs layout [k][n] stride 136 (conflict-free).
// Requires M%128==0, N%128==0, K%16==0 (true for all calls).
// ---------------------------------------------------------------------------
#define GSA 20
#define GSB 136

__global__ void __launch_bounds__(256, 2)
tc_gemm(int K,
        const float* __restrict__ A, int lda,
        const float* __restrict__ B, int ldb,
        float*       __restrict__ C, int ldc)
{
    __shared__ float As[2][128 * GSA];
    __shared__ float Bs[2][16 * GSB];

    const int tid  = threadIdx.x;
    const int warp = tid >> 5;
    const int lane = tid & 31;
    const int wm   = warp >> 1;       // 0..3
    const int wn   = warp & 1;        // 0..1
    const int g    = lane >> 2;       // 0..7
    const int t    = lane & 3;        // 0..3

    const int m0 = blockIdx.y * 128;
    const int n0 = blockIdx.x * 128;

    const int rA = tid >> 1;          // 0..127
    const int cA = (tid & 1) * 8;     // 0 or 8
    const int kB = tid >> 4;          // 0..15
    const int nB = (tid & 15) * 8;    // 0..120

    const float* Ap = A + (size_t)(m0 + rA) * lda + cA;
    const float* Bp = B + (size_t)kB * ldb + n0 + nB;

    float acc[2][8][4] = {};

    // stage 0
    cp_async16(&As[0][rA * GSA + cA],     Ap);
    cp_async16(&As[0][rA * GSA + cA + 4], Ap + 4);
    cp_async16(&Bs[0][kB * GSB + nB],     Bp);
    cp_async16(&Bs[0][kB * GSB + nB + 4], Bp + 4);
    cp_commit();
    Ap += 16; Bp += (size_t)16 * ldb;

    const int nt = K >> 4;
    for (int kt = 0; kt < nt; kt++) {
        cp_wait<0>();
        __syncthreads();
        if (kt + 1 < nt) {
            const int s = (kt + 1) & 1;
            cp_async16(&As[s][rA * GSA + cA],     Ap);
            cp_async16(&As[s][rA * GSA + cA + 4], Ap + 4);
            cp_async16(&Bs[s][kB * GSB + nB],     Bp);
            cp_async16(&Bs[s][kB * GSB + nB + 4], Bp + 4);
            cp_commit();
            Ap += 16; Bp += (size_t)16 * ldb;
        }
        const float* as = As[kt & 1];
        const float* bs = Bs[kt & 1];
        #pragma unroll
        for (int ks = 0; ks < 2; ks++) {
            const int kb = ks * 8;
            uint32_t af[2][4];
            #pragma unroll
            for (int mi = 0; mi < 2; mi++) {
                const int row = wm * 32 + mi * 16;
                af[mi][0] = __float_as_uint(as[(row + g)     * GSA + kb + t]);
                af[mi][1] = __float_as_uint(as[(row + g + 8) * GSA + kb + t]);
                af[mi][2] = __float_as_uint(as[(row + g)     * GSA + kb + t + 4]);
                af[mi][3] = __float_as_uint(as[(row + g + 8) * GSA + kb + t + 4]);
            }
            #pragma unroll
            for (int ni = 0; ni < 8; ni++) {
                const int col = wn * 64 + ni * 8 + g;
                uint32_t bf[2] = { __float_as_uint(bs[(kb + t)     * GSB + col]),
                                   __float_as_uint(bs[(kb + t + 4) * GSB + col]) };
                #pragma unroll
                for (int mi = 0; mi < 2; mi++)
                    mma_tf32(acc[mi][ni], af[mi], bf);
            }
        }
    }

    #pragma unroll
    for (int mi = 0; mi < 2; mi++) {
        #pragma unroll
        for (int ni = 0; ni < 8; ni++) {
            const int r = m0 + wm * 32 + mi * 16 + g;
            const int c = n0 + wn * 64 + ni * 8 + t * 2;
            *(float2*)&C[(size_t)r * ldc + c] =
                make_float2(acc[mi][ni][0], acc[mi][ni][1]);
            *(float2*)&C[(size_t)(r + 8) * ldc + c] =
                make_float2(acc[mi][ni][2], acc[mi][ni][3]);
        }
    }
}

// ---------------------------------------------------------------------------
// Fused tensor-core flash attention (K/V shared across heads).
// q:   [BTOK, NH, DH]   kv: [BTOK, 2*DH] (K in cols 0..63, V in 64..127)
// out: [BTOK, NH, DH]
// grid (SEQ/128, NH, BATCH), 256 threads = 8 warps; warp w owns rows w*16..+15.
// 64-key tiles; Q frags live in registers; P converted c-frag->a-frag by shfl.
// ---------------------------------------------------------------------------
#define FS 68   // smem stride for K/V tiles (conflict-free: 4g+t distinct mod 32)

__global__ void __launch_bounds__(256, 1)
flash_kernel(const float* __restrict__ q,
             const float* __restrict__ kv,
             float* __restrict__ out)
{
    __shared__ float Ks[64 * FS];
    __shared__ float Vs[64 * FS];

    const int tid  = threadIdx.x;
    const int warp = tid >> 5;
    const int lane = tid & 31;
    const int g    = lane >> 2;      // 0..7
    const int t    = lane & 3;       // 0..3
    const int b    = blockIdx.z;
    const int h    = blockIdx.y;
    const int q0   = blockIdx.x * 128;
    const int row0 = q0 + warp * 16;

    // Q a-frags: 8 k8-chunks covering dh=64
    uint32_t aQ[8][4];
    {
        const float* Qb = q + ((size_t)b * SEQ + row0) * DMODEL + h * DH;
        #pragma unroll
        for (int kk = 0; kk < 8; kk++) {
            aQ[kk][0] = __float_as_uint(Qb[(size_t)g       * DMODEL + kk * 8 + t]);
            aQ[kk][1] = __float_as_uint(Qb[(size_t)(g + 8) * DMODEL + kk * 8 + t]);
            aQ[kk][2] = __float_as_uint(Qb[(size_t)g       * DMODEL + kk * 8 + t + 4]);
            aQ[kk][3] = __float_as_uint(Qb[(size_t)(g + 8) * DMODEL + kk * 8 + t + 4]);
        }
    }

    float m0v = -1e30f, m1v = -1e30f;   // running row max (rows g, g+8)
    float l0 = 0.f, l1 = 0.f;           // running denominators
    float O[8][4] = {};                 // out accum: [dh-block ni][c-frag]

    const float* kvb = kv + (size_t)b * SEQ * 128;
    const int r  = tid >> 2;            // 0..63 (staging row)
    const int cc = (tid & 3) * 16;      // staging col base

    for (int j0 = 0; j0 < SEQ; j0 += 64) {
        __syncthreads();   // previous tile's Ks/Vs reads complete
        {
            const float* srck = kvb + (size_t)(j0 + r) * 128 + cc;
            const float* srcv = srck + 64;
            #pragma unroll
            for (int i = 0; i < 4; i++)
                *(float4*)&Ks[r * FS + cc + i * 4] = *(const float4*)(srck + i * 4);
            #pragma unroll
            for (int i = 0; i < 4; i++)
                *(float4*)&Vs[r * FS + cc + i * 4] = *(const float4*)(srcv + i * 4);
        }
        __syncthreads();

        // ---- S = Q @ K^T : sacc[ni] covers keys ni*8..+7 for rows g,g+8 ----
        float sacc[8][4] = {};
        #pragma unroll
        for (int kk = 0; kk < 8; kk++) {
            #pragma unroll
            for (int ni = 0; ni < 8; ni++) {
                uint32_t bk[2] = {
                    __float_as_uint(Ks[(ni * 8 + g) * FS + kk * 8 + t]),
                    __float_as_uint(Ks[(ni * 8 + g) * FS + kk * 8 + t + 4]) };
                mma_tf32(sacc[ni], aQ[kk], bk);
            }
        }

        // ---- online softmax ----
        const float sc = 0.125f;  // 1/sqrt(64)
        float mt0 = -1e30f, mt1 = -1e30f;
        #pragma unroll
        for (int ni = 0; ni < 8; ni++) {
            sacc[ni][0] *= sc; sacc[ni][1] *= sc;
            sacc[ni][2] *= sc; sacc[ni][3] *= sc;
            mt0 = fmaxf(mt0, fmaxf(sacc[ni][0], sacc[ni][1]));
            mt1 = fmaxf(mt1, fmaxf(sacc[ni][2], sacc[ni][3]));
        }
        mt0 = fmaxf(mt0, __shfl_xor_sync(0xffffffffu, mt0, 1));
        mt0 = fmaxf(mt0, __shfl_xor_sync(0xffffffffu, mt0, 2));
        mt1 = fmaxf(mt1, __shfl_xor_sync(0xffffffffu, mt1, 1));
        mt1 = fmaxf(mt1, __shfl_xor_sync(0xffffffffu, mt1, 2));

        const float mn0 = fmaxf(m0v, mt0);
        const float mn1 = fmaxf(m1v, mt1);
        const float f0  = __expf(m0v - mn0);
        const float f1  = __expf(m1v - mn1);
        float ts0 = 0.f, ts1 = 0.f;
        #pragma unroll
        for (int ni = 0; ni < 8; ni++) {
            sacc[ni][0] = __expf(sacc[ni][0] - mn0);
            sacc[ni][1] = __expf(sacc[ni][1] - mn0);
            sacc[ni][2] = __expf(sacc[ni][2] - mn1);
            sacc[ni][3] = __expf(sacc[ni][3] - mn1);
            ts0 += sacc[ni][0] + sacc[ni][1];
            ts1 += sacc[ni][2] + sacc[ni][3];
        }
        ts0 += __shfl_xor_sync(0xffffffffu, ts0, 1);
        ts0 += __shfl_xor_sync(0xffffffffu, ts0, 2);
        ts1 += __shfl_xor_sync(0xffffffffu, ts1, 1);
        ts1 += __shfl_xor_sync(0xffffffffu, ts1, 2);

        l0 = l0 * f0 + ts0;
        l1 = l1 * f1 + ts1;
        m0v = mn0; m1v = mn1;
        #pragma unroll
        for (int ni = 0; ni < 8; ni++) {
            O[ni][0] *= f0; O[ni][1] *= f0;
            O[ni][2] *= f1; O[ni][3] *= f1;
        }

        // ---- O += P @ V : convert P c-frag -> a-frag via quad shfl ----
        const int s_lo = (lane & ~3) | (t >> 1);
        const int s_hi = s_lo + 2;
        const bool odd = (t & 1);
        #pragma unroll
        for (int kb = 0; kb < 8; kb++) {
            const float v00 = __shfl_sync(0xffffffffu, sacc[kb][0], s_lo);
            const float v01 = __shfl_sync(0xffffffffu, sacc[kb][1], s_lo);
            const float v10 = __shfl_sync(0xffffffffu, sacc[kb][2], s_lo);
            const float v11 = __shfl_sync(0xffffffffu, sacc[kb][3], s_lo);
            const float w00 = __shfl_sync(0xffffffffu, sacc[kb][0], s_hi);
            const float w01 = __shfl_sync(0xffffffffu, sacc[kb][1], s_hi);
            const float w10 = __shfl_sync(0xffffffffu, sacc[kb][2], s_hi);
            const float w11 = __shfl_sync(0xffffffffu, sacc[kb][3], s_hi);
            uint32_t aP[4];
            aP[0] = __float_as_uint(odd ? v01 : v00);   // P[g   ][8kb + t]
            aP[1] = __float_as_uint(odd ? v11 : v10);   // P[g+8 ][8kb + t]
            aP[2] = __float_as_uint(odd ? w01 : w00);   // P[g   ][8kb + t+4]
            aP[3] = __float_as_uint(odd ? w11 : w10);   // P[g+8 ][8kb + t+4]
            #pragma unroll
            for (int ni = 0; ni < 8; ni++) {
                uint32_t bv[2] = {
                    __float_as_uint(Vs[(kb * 8 + t)     * FS + ni * 8 + g]),
                    __float_as_uint(Vs[(kb * 8 + t + 4) * FS + ni * 8 + g]) };
                mma_tf32(O[ni], aP, bv);
            }
        }
    }

    // ---- epilogue ----
    const float inv0 = 1.f / l0;
    const float inv1 = 1.f / l1;
    float* ob = out + ((size_t)b * SEQ + row0) * DMODEL + h * DH;
    #pragma unroll
    for (int ni = 0; ni < 8; ni++) {
        *(float2*)&ob[(size_t)g       * DMODEL + ni * 8 + 2 * t] =
            make_float2(O[ni][0] * inv0, O[ni][1] * inv0);
        *(float2*)&ob[(size_t)(g + 8) * DMODEL + ni * 8 + 2 * t] =
            make_float2(O[ni][2] * inv1, O[ni][3] * inv1);
    }
}

// ---------------------------------------------------------------------------
// Block reduce (256 threads)
// ---------------------------------------------------------------------------
__device__ __forceinline__ float block_reduce_sum(float v, float* scratch)
{
    __syncthreads();
    const int lane = threadIdx.x & 31;
    const int w    = threadIdx.x >> 5;
    #pragma unroll
    for (int off = 16; off; off >>= 1) v += __shfl_xor_sync(0xffffffffu, v, off);
    if (lane == 0) scratch[w] = v;
    __syncthreads();
    if (w == 0) {
        float x = (lane < 8) ? scratch[lane] : 0.f;
        #pragma unroll
        for (int off = 4; off; off >>= 1) x += __shfl_xor_sync(0xffffffffu, x, off);
        if (lane == 0) scratch[0] = x;
    }
    __syncthreads();
    return scratch[0];
}

// ---------------------------------------------------------------------------
// x1 = LN(x + proj) * gamma1 ;  h = LN(x1) * gamma_ffn
// ---------------------------------------------------------------------------
__global__ void __launch_bounds__(256)
ln_dual_kernel(const float* __restrict__ x, const float* __restrict__ pj,
               const float* __restrict__ g1, const float* __restrict__ gf,
               float* __restrict__ x1, float* __restrict__ h)
{
    __shared__ float buf[DMODEL];
    __shared__ float scr[32];
    const size_t row = blockIdx.x;
    const float* xr = x  + row * DMODEL;
    const float* pr = pj + row * DMODEL;

    float sum = 0.f, sq = 0.f;
    for (int i = threadIdx.x; i < DMODEL; i += 256) {
        const float v = xr[i] + pr[i];
        buf[i] = v; sum += v; sq += v * v;
    }
    sum = block_reduce_sum(sum, scr);
    sq  = block_reduce_sum(sq,  scr);
    const float mu  = sum * (1.f / DMODEL);
    const float var = sq * (1.f / DMODEL) - mu * mu;
    const float rs  = rsqrtf(var + LN_EPS);

    float sum2 = 0.f, sq2 = 0.f;
    for (int i = threadIdx.x; i < DMODEL; i += 256) {
        const float v = (buf[i] - mu) * rs * g1[i];
        x1[row * DMODEL + i] = v;
        buf[i] = v; sum2 += v; sq2 += v * v;
    }
    sum2 = block_reduce_sum(sum2, scr);
    sq2  = block_reduce_sum(sq2,  scr);
    const float mu2  = sum2 * (1.f / DMODEL);
    const float var2 = sq2 * (1.f / DMODEL) - mu2 * mu2;
    const float rs2  = rsqrtf(var2 + LN_EPS);

    for (int i = threadIdx.x; i < DMODEL; i += 256)
        h[row * DMODEL + i] = (buf[i] - mu2) * rs2 * gf[i];
}

// ---------------------------------------------------------------------------
// out = LN(a + b) * gamma
// ---------------------------------------------------------------------------
__global__ void __launch_bounds__(256)
ln_final_kernel(const float* __restrict__ a, const float* __restrict__ bb,
                const float* __restrict__ gm, float* __restrict__ outp)
{
    __shared__ float buf[DMODEL];
    __shared__ float scr[32];
    const size_t row = blockIdx.x;
    const float* ar = a  + row * DMODEL;
    const float* br = bb + row * DMODEL;

    float sum = 0.f, sq = 0.f;
    for (int i = threadIdx.x; i < DMODEL; i += 256) {
        const float v = ar[i] + br[i];
        buf[i] = v; sum += v; sq += v * v;
    }
    sum = block_reduce_sum(sum, scr);
    sq  = block_reduce_sum(sq,  scr);
    const float mu  = sum * (1.f / DMODEL);
    const float var = sq * (1.f / DMODEL) - mu * mu;
    const float rs  = rsqrtf(var + LN_EPS);

    for (int i = threadIdx.x; i < DMODEL; i += 256)
        outp[row * DMODEL + i] = (buf[i] - mu) * rs * gm[i];
}

// ---------------------------------------------------------------------------
// f = gelu_exact(u[:, INNER:]) * u[:, :INNER]
// ---------------------------------------------------------------------------
__global__ void __launch_bounds__(256)
gelu_mul_kernel(const float* __restrict__ u, float* __restrict__ f)
{
    const size_t idx = (size_t)blockIdx.x * blockDim.x + threadIdx.x;
    const size_t n4  = (size_t)BTOK * INNER / 4;
    if (idx >= n4) return;
    const size_t e   = idx * 4;
    const size_t row = e >> 12;
    const size_t col = e & (INNER - 1);
    const float4 a  = *(const float4*)(u + row * (2 * INNER) + col);
    const float4 gt = *(const float4*)(u + row * (2 * INNER) + INNER + col);
    float4 rv;
    rv.x = 0.5f * gt.x * (1.f + erff(gt.x * 0.70710678118654752f)) * a.x;
    rv.y = 0.5f * gt.y * (1.f + erff(gt.y * 0.70710678118654752f)) * a.y;
    rv.z = 0.5f * gt.z * (1.f + erff(gt.z * 0.70710678118654752f)) * a.z;
    rv.w = 0.5f * gt.w * (1.f + erff(gt.w * 0.70710678118654752f)) * a.w;
    *(float4*)(f + e) = rv;
}

// ---------------------------------------------------------------------------
// Launch
// ---------------------------------------------------------------------------
extern "C" void kernel_launch(void* const* d_in, const int* in_sizes, int n_in,
                              void* d_out, int out_size)
{
    const float* x        = (const float*)d_in[0];
    const float* w_q      = (const float*)d_in[1];
    const float* w_kv     = (const float*)d_in[2];
    const float* w_concat = (const float*)d_in[3];
    const float* gamma1   = (const float*)d_in[4];
    const float* gammaffn = (const float*)d_in[5];
    const float* w_ff1    = (const float*)d_in[6];
    const float* w_ff2    = (const float*)d_in[7];
    const float* gamma2   = (const float*)d_in[8];
    float* out = (float*)d_out;

    float *q, *kvp, *attn, *proj, *x1, *h, *u, *f, *ffn;
    cudaGetSymbolAddress((void**)&q,    g_q);
    cudaGetSymbolAddress((void**)&kvp,  g_kv);
    cudaGetSymbolAddress((void**)&attn, g_attn);
    cudaGetSymbolAddress((void**)&proj, g_proj);
    cudaGetSymbolAddress((void**)&x1,   g_x1);
    cudaGetSymbolAddress((void**)&h,    g_h);
    cudaGetSymbolAddress((void**)&u,    g_u);
    cudaGetSymbolAddress((void**)&f,    g_f);
    cudaGetSymbolAddress((void**)&ffn,  g_ffn);

    // 1) q = x @ w_q   [4096,1024]
    tc_gemm<<<dim3(8, 32), 256>>>(DMODEL, x, DMODEL, w_q, DMODEL, q, DMODEL);
    // 2) kv = x @ w_kv [4096,128]
    tc_gemm<<<dim3(1, 32), 256>>>(DMODEL, x, DMODEL, w_kv, 128, kvp, 128);
    // 3) fused flash attention
    flash_kernel<<<dim3(SEQ / 128, NH, BATCH), 256>>>(q, kvp, attn);
    // 4) proj = attn @ w_concat
    tc_gemm<<<dim3(8, 32), 256>>>(DMODEL, attn, DMODEL, w_concat, DMODEL, proj, DMODEL);
    // 5) x1 = LN(x+proj)*g1 ; h = LN(x1)*gffn
    ln_dual_kernel<<<BTOK, 256>>>(x, proj, gamma1, gammaffn, x1, h);
    // 6) u = h @ w_ff1 [4096,8192]
    tc_gemm<<<dim3(64, 32), 256>>>(DMODEL, h, DMODEL, w_ff1, 2 * INNER, u, 2 * INNER);
    // 7) f = gelu(gate)*a
    {
        const size_t n4 = (size_t)BTOK * INNER / 4;
        gelu_mul_kernel<<<(unsigned)((n4 + 255) / 256), 256>>>(u, f);
    }
    // 8) ffn = f @ w_ff2 [4096,1024]
    tc_gemm<<<dim3(8, 32), 256>>>(INNER, f, INNER, w_ff2, DMODEL, ffn, DMODEL);
    // 9) out = LN(x1+ffn)*g2
    ln_final_kernel<<<BTOK, 256>>>(x1, ffn, gamma2, out);
}